// round 1
// baseline (speedup 1.0000x reference)
#include <cuda_runtime.h>
#include <cuda_bf16.h>

// Problem constants (static shapes from reference)
#define NUM_EXPERTS 64
#define DIM 2048
#define HIDDEN 1024
#define TOK_PER_E 256
#define TOTAL_TOKENS (NUM_EXPERTS * TOK_PER_E)

// SGEMM tiling
#define BM 128
#define BN 128
#define BK 16
#define TM 8
#define TN 8
#define NTHREADS 256

// Scratch: gate and up projections (64 MB each), static device arrays (no allocs)
__device__ float g_gate[TOTAL_TOKENS * HIDDEN];
__device__ float g_up[TOTAL_TOKENS * HIDDEN];

// Batched SGEMM: C[z] = A[z] @ B[z]
// A: [M x K] row-major, B: [K x N] row-major, C: [M x N] row-major.
// Grid: (N/BN, M/BM, NUM_EXPERTS). All dims exact multiples of tiles.
__global__ __launch_bounds__(NTHREADS, 2)
void sgemm_batched(const float* __restrict__ A, const float* __restrict__ B,
                   float* __restrict__ C,
                   int M, int N, int K,
                   long long strideA, long long strideB, long long strideC)
{
    __shared__ float As[BK][BM + 4];   // transposed A tile, padded
    __shared__ float Bs[BK][BN];

    const int tid = threadIdx.x;
    const int tx = tid & 15;           // 0..15 -> column group
    const int ty = tid >> 4;           // 0..15 -> row group

    const int rowBase = blockIdx.y * BM;
    const int colBase = blockIdx.x * BN;

    A += (long long)blockIdx.z * strideA;
    B += (long long)blockIdx.z * strideB;
    C += (long long)blockIdx.z * strideC;

    // A tile loader: 128 rows x 16 k = 128x4 float4; 512 f4 / 256 thr = 2 each
    const int rowA0 = tid >> 2;              // 0..63
    const int kc4_0 = tid & 3;               // which float4 along k
    const int rowA1 = (tid + 256) >> 2;      // 64..127
    const int kc4_1 = (tid + 256) & 3;

    // B tile loader: 16 k-rows x 128 cols = 16x32 float4; 2 each
    const int rowB0 = tid >> 5;              // 0..7
    const int cc4_0 = tid & 31;
    const int rowB1 = (tid + 256) >> 5;      // 8..15
    const int cc4_1 = (tid + 256) & 31;

    float acc[TM][TN];
    #pragma unroll
    for (int i = 0; i < TM; i++)
        #pragma unroll
        for (int j = 0; j < TN; j++)
            acc[i][j] = 0.f;

    for (int kt = 0; kt < K; kt += BK) {
        // Global loads into registers first (overlap with previous compute drain)
        float4 a0 = *(const float4*)&A[(long long)(rowBase + rowA0) * K + kt + kc4_0 * 4];
        float4 a1 = *(const float4*)&A[(long long)(rowBase + rowA1) * K + kt + kc4_1 * 4];
        float4 b0 = *(const float4*)&B[(long long)(kt + rowB0) * N + colBase + cc4_0 * 4];
        float4 b1 = *(const float4*)&B[(long long)(kt + rowB1) * N + colBase + cc4_1 * 4];

        __syncthreads();  // previous iteration's compute done before overwrite

        // Store A transposed: As[k][m]
        As[kc4_0 * 4 + 0][rowA0] = a0.x;
        As[kc4_0 * 4 + 1][rowA0] = a0.y;
        As[kc4_0 * 4 + 2][rowA0] = a0.z;
        As[kc4_0 * 4 + 3][rowA0] = a0.w;
        As[kc4_1 * 4 + 0][rowA1] = a1.x;
        As[kc4_1 * 4 + 1][rowA1] = a1.y;
        As[kc4_1 * 4 + 2][rowA1] = a1.z;
        As[kc4_1 * 4 + 3][rowA1] = a1.w;

        *(float4*)&Bs[rowB0][cc4_0 * 4] = b0;
        *(float4*)&Bs[rowB1][cc4_1 * 4] = b1;

        __syncthreads();

        #pragma unroll
        for (int k = 0; k < BK; k++) {
            float ar[TM], br[TN];
            float4 av0 = *(const float4*)&As[k][ty * TM];
            float4 av1 = *(const float4*)&As[k][ty * TM + 4];
            float4 bv0 = *(const float4*)&Bs[k][tx * TN];
            float4 bv1 = *(const float4*)&Bs[k][tx * TN + 4];
            ar[0]=av0.x; ar[1]=av0.y; ar[2]=av0.z; ar[3]=av0.w;
            ar[4]=av1.x; ar[5]=av1.y; ar[6]=av1.z; ar[7]=av1.w;
            br[0]=bv0.x; br[1]=bv0.y; br[2]=bv0.z; br[3]=bv0.w;
            br[4]=bv1.x; br[5]=bv1.y; br[6]=bv1.z; br[7]=bv1.w;
            #pragma unroll
            for (int i = 0; i < TM; i++)
                #pragma unroll
                for (int j = 0; j < TN; j++)
                    acc[i][j] = fmaf(ar[i], br[j], acc[i][j]);
        }
    }

    // Write C: 8 rows x 8 cols per thread as 2x float4 per row
    #pragma unroll
    for (int i = 0; i < TM; i++) {
        long long row = rowBase + ty * TM + i;
        float4 o0 = make_float4(acc[i][0], acc[i][1], acc[i][2], acc[i][3]);
        float4 o1 = make_float4(acc[i][4], acc[i][5], acc[i][6], acc[i][7]);
        *(float4*)&C[row * N + colBase + tx * TN]     = o0;
        *(float4*)&C[row * N + colBase + tx * TN + 4] = o1;
    }
}

// h = silu(gate) * up, in-place into gate. n is in float4 units.
__global__ void silu_mul_kernel(float4* __restrict__ gate,
                                const float4* __restrict__ up, int n4)
{
    int idx = blockIdx.x * blockDim.x + threadIdx.x;
    int stride = gridDim.x * blockDim.x;
    for (int i = idx; i < n4; i += stride) {
        float4 g = gate[i];
        float4 u = up[i];
        float4 h;
        h.x = (g.x / (1.f + expf(-g.x))) * u.x;
        h.y = (g.y / (1.f + expf(-g.y))) * u.y;
        h.z = (g.z / (1.f + expf(-g.z))) * u.z;
        h.w = (g.w / (1.f + expf(-g.w))) * u.w;
        gate[i] = h;
    }
}

extern "C" void kernel_launch(void* const* d_in, const int* in_sizes, int n_in,
                              void* d_out, int out_size)
{
    const float* x  = (const float*)d_in[0];
    const float* w1 = (const float*)d_in[1];
    const float* w2 = (const float*)d_in[2];
    const float* w3 = (const float*)d_in[3];
    // d_in[4] = num_local_tokens_per_expert (static equal counts, unused)
    float* out = (float*)d_out;

    float* gate = nullptr;
    float* up = nullptr;
    cudaGetSymbolAddress((void**)&gate, g_gate);
    cudaGetSymbolAddress((void**)&up, g_up);

    // Stage 1: gate = x @ w1[e], up = x @ w3[e]   (M=256, N=1024, K=2048 per expert)
    {
        dim3 grid(HIDDEN / BN, TOK_PER_E / BM, NUM_EXPERTS);
        sgemm_batched<<<grid, NTHREADS>>>(x, w1, gate,
                                          TOK_PER_E, HIDDEN, DIM,
                                          (long long)TOK_PER_E * DIM,
                                          (long long)DIM * HIDDEN,
                                          (long long)TOK_PER_E * HIDDEN);
        sgemm_batched<<<grid, NTHREADS>>>(x, w3, up,
                                          TOK_PER_E, HIDDEN, DIM,
                                          (long long)TOK_PER_E * DIM,
                                          (long long)DIM * HIDDEN,
                                          (long long)TOK_PER_E * HIDDEN);
    }

    // Stage 2: h = silu(gate) * up  (in-place into gate)
    {
        int n4 = TOTAL_TOKENS * HIDDEN / 4;
        silu_mul_kernel<<<2048, 256>>>((float4*)gate, (const float4*)up, n4);
    }

    // Stage 3: out = h @ w2[e]   (M=256, N=2048, K=1024 per expert)
    {
        dim3 grid(DIM / BN, TOK_PER_E / BM, NUM_EXPERTS);
        sgemm_batched<<<grid, NTHREADS>>>(gate, w2, out,
                                          TOK_PER_E, DIM, HIDDEN,
                                          (long long)TOK_PER_E * HIDDEN,
                                          (long long)HIDDEN * DIM,
                                          (long long)TOK_PER_E * DIM);
    }
}

// round 3
// speedup vs baseline: 3.5246x; 3.5246x over previous
#include <cuda_runtime.h>
#include <cuda_bf16.h>
#include <cstdint>

// ---------------- problem constants ----------------
#define NUM_EXPERTS 64
#define DIM 2048
#define HIDDEN 1024
#define TOK_PER_E 256
#define TOTAL_TOKENS (NUM_EXPERTS * TOK_PER_E)

#define NTHREADS 256

// h scratch (fp32, 64 MB)
__device__ float g_h[(size_t)TOTAL_TOKENS * HIDDEN];

// ---------------- smem layout ----------------
// A tile: 128 rows x 32 k, pitch 36 words (144 B)   -> conflict-free LDS
// B tile: 32 k-rows x N cols, pitch N+8 words       -> conflict-free LDS
#define A_PITCH_W 36
#define A_BYTES (128 * A_PITCH_W * 4)          // 18432
#define B64_PITCH_W 72
#define B64_BYTES (32 * B64_PITCH_W * 4)       // 9216
#define B128_PITCH_W 136
#define B128_BYTES (32 * B128_PITCH_W * 4)     // 17408

#define GU_STAGE (A_BYTES + 2 * B64_BYTES)     // 36864
#define DN_STAGE (A_BYTES + B128_BYTES)        // 35840
#define GU_SMEM (2 * GU_STAGE)                 // 73728
#define DN_SMEM (2 * DN_STAGE)                 // 71680

// ---------------- PTX helpers ----------------
__device__ __forceinline__ uint32_t smem_u32(const void* p) {
    uint32_t a;
    asm("{ .reg .u64 t; cvta.to.shared.u64 t, %1; cvt.u32.u64 %0, t; }" : "=r"(a) : "l"(p));
    return a;
}
__device__ __forceinline__ uint32_t tf32r(float v) {
    uint32_t o; asm("cvt.rna.tf32.f32 %0, %1;" : "=r"(o) : "f"(v)); return o;
}
__device__ __forceinline__ void cp_async16(uint32_t dst, const void* src) {
    asm volatile("cp.async.cg.shared.global [%0], [%1], 16;" :: "r"(dst), "l"(src));
}
__device__ __forceinline__ void cp_commit() {
    asm volatile("cp.async.commit_group;" ::: "memory");
}
template <int N>
__device__ __forceinline__ void cp_wait() {
    asm volatile("cp.async.wait_group %0;" :: "n"(N) : "memory");
}
__device__ __forceinline__ void mma_tf32(float d[4], const uint32_t a[4],
                                         uint32_t b0, uint32_t b1) {
    asm volatile(
        "mma.sync.aligned.m16n8k8.row.col.f32.tf32.tf32.f32 "
        "{%0,%1,%2,%3}, {%4,%5,%6,%7}, {%8,%9}, {%0,%1,%2,%3};"
        : "+f"(d[0]), "+f"(d[1]), "+f"(d[2]), "+f"(d[3])
        : "r"(a[0]), "r"(a[1]), "r"(a[2]), "r"(a[3]), "r"(b0), "r"(b1));
}

// ================= fused gate/up + SiLU =================
// BM=128, BN=64 (per matrix), BK=32. 8 warps: wm=wid>>1 (4), wn=wid&1 (2).
// Warp tile 32 x 32 per matrix: mi in {0,1} (m16), ni in 0..3 (n8).
__global__ __launch_bounds__(NTHREADS, 2)
void moe_gateup(const float* __restrict__ x, const float* __restrict__ w1,
                const float* __restrict__ w3, float* __restrict__ h)
{
    extern __shared__ char smem[];
    const int tid = threadIdx.x, lane = tid & 31, wid = tid >> 5;
    const int wm = wid >> 1, wn = wid & 1, g = lane >> 2, c = lane & 3;
    const int e = blockIdx.z, mt = blockIdx.y, nt = blockIdx.x;

    const float* xe  = x  + ((long long)e * TOK_PER_E + mt * 128) * DIM;
    const float* w1e = w1 + (long long)e * DIM * HIDDEN + nt * 64;
    const float* w3e = w3 + (long long)e * DIM * HIDDEN + nt * 64;

    auto load_stage = [&](int buf, int kt) {
        uint32_t sA = smem_u32(smem + buf * GU_STAGE);
        // A: 128x32 fp32 = 1024 16B-chunks, 4 per thread
#pragma unroll
        for (int j = 0; j < 4; j++) {
            int id = tid + 256 * j;
            int r = id >> 3, c4 = id & 7;
            cp_async16(sA + r * 144 + c4 * 16, xe + (long long)r * DIM + kt + c4 * 4);
        }
        uint32_t sB1 = sA + A_BYTES, sB3 = sB1 + B64_BYTES;
        // B: 32x64 fp32 = 512 chunks each, 2 per thread
#pragma unroll
        for (int j = 0; j < 2; j++) {
            int id = tid + 256 * j;
            int k = id >> 4, c4 = id & 15;
            cp_async16(sB1 + k * 288 + c4 * 16, w1e + (long long)(kt + k) * HIDDEN + c4 * 4);
            cp_async16(sB3 + k * 288 + c4 * 16, w3e + (long long)(kt + k) * HIDDEN + c4 * 4);
        }
        cp_commit();
    };

    float accG[2][4][4] = {}, accU[2][4][4] = {};

    load_stage(0, 0);
    load_stage(1, 32);

    const int NIT = DIM / 32;  // 64
    for (int it = 0; it < NIT; ++it) {
        const int buf = it & 1;
        if (it == NIT - 1) cp_wait<0>(); else cp_wait<1>();
        __syncthreads();

        const float* As  = (const float*)(smem + buf * GU_STAGE);
        const float* B1s = As + 128 * A_PITCH_W;
        const float* B3s = B1s + 32 * B64_PITCH_W;

#pragma unroll
        for (int s = 0; s < 4; s++) {
            const int k0 = 8 * s + c;
            uint32_t a[2][4];
#pragma unroll
            for (int mi = 0; mi < 2; mi++) {
                const float* ap = As + (wm * 32 + mi * 16 + g) * A_PITCH_W + k0;
                a[mi][0] = tf32r(ap[0]);
                a[mi][1] = tf32r(ap[8 * A_PITCH_W]);
                a[mi][2] = tf32r(ap[4]);
                a[mi][3] = tf32r(ap[8 * A_PITCH_W + 4]);
            }
#pragma unroll
            for (int ni = 0; ni < 4; ni++) {
                const int nb = wn * 32 + ni * 8 + g;
                {
                    const float* bp = B1s + k0 * B64_PITCH_W + nb;
                    uint32_t b0 = tf32r(bp[0]), b1v = tf32r(bp[4 * B64_PITCH_W]);
                    mma_tf32(accG[0][ni], a[0], b0, b1v);
                    mma_tf32(accG[1][ni], a[1], b0, b1v);
                }
                {
                    const float* bp = B3s + k0 * B64_PITCH_W + nb;
                    uint32_t b0 = tf32r(bp[0]), b1v = tf32r(bp[4 * B64_PITCH_W]);
                    mma_tf32(accU[0][ni], a[0], b0, b1v);
                    mma_tf32(accU[1][ni], a[1], b0, b1v);
                }
            }
        }
        __syncthreads();
        if (it + 2 < NIT) load_stage(buf, (it + 2) * 32);
    }

    // epilogue: h = silu(gate) * up
    const int colbase = nt * 64 + wn * 32;
    const long long rowbase = (long long)e * TOK_PER_E + mt * 128 + wm * 32;
#pragma unroll
    for (int mi = 0; mi < 2; mi++) {
        const long long r0 = rowbase + mi * 16 + g;
#pragma unroll
        for (int ni = 0; ni < 4; ni++) {
            const int col = colbase + ni * 8 + 2 * c;
            float* p0 = h + r0 * HIDDEN + col;
            float* p1 = p0 + 8 * HIDDEN;
            float gv, uv; float2 o;
            gv = accG[mi][ni][0]; uv = accU[mi][ni][0];
            o.x = gv / (1.f + __expf(-gv)) * uv;
            gv = accG[mi][ni][1]; uv = accU[mi][ni][1];
            o.y = gv / (1.f + __expf(-gv)) * uv;
            *(float2*)p0 = o;
            gv = accG[mi][ni][2]; uv = accU[mi][ni][2];
            o.x = gv / (1.f + __expf(-gv)) * uv;
            gv = accG[mi][ni][3]; uv = accU[mi][ni][3];
            o.y = gv / (1.f + __expf(-gv)) * uv;
            *(float2*)p1 = o;
        }
    }
}

// ================= down-projection =================
// BM=128, BN=128, BK=32. Warp tile 32 x 64: mi in {0,1}, ni in 0..7.
__global__ __launch_bounds__(NTHREADS, 2)
void moe_down(const float* __restrict__ h, const float* __restrict__ w2,
              float* __restrict__ out)
{
    extern __shared__ char smem[];
    const int tid = threadIdx.x, lane = tid & 31, wid = tid >> 5;
    const int wm = wid >> 1, wn = wid & 1, g = lane >> 2, c = lane & 3;
    const int e = blockIdx.z, mt = blockIdx.y, nt = blockIdx.x;

    const float* he  = h  + ((long long)e * TOK_PER_E + mt * 128) * HIDDEN;
    const float* w2e = w2 + (long long)e * HIDDEN * DIM + nt * 128;

    auto load_stage = [&](int buf, int kt) {
        uint32_t sA = smem_u32(smem + buf * DN_STAGE);
#pragma unroll
        for (int j = 0; j < 4; j++) {
            int id = tid + 256 * j;
            int r = id >> 3, c4 = id & 7;
            cp_async16(sA + r * 144 + c4 * 16, he + (long long)r * HIDDEN + kt + c4 * 4);
        }
        uint32_t sB = sA + A_BYTES;
        // B: 32x128 fp32 = 1024 chunks, 4 per thread
#pragma unroll
        for (int j = 0; j < 4; j++) {
            int id = tid + 256 * j;
            int k = id >> 5, c4 = id & 31;
            cp_async16(sB + k * 544 + c4 * 16, w2e + (long long)(kt + k) * DIM + c4 * 4);
        }
        cp_commit();
    };

    float acc[2][8][4] = {};

    load_stage(0, 0);
    load_stage(1, 32);

    const int NIT = HIDDEN / 32;  // 32
    for (int it = 0; it < NIT; ++it) {
        const int buf = it & 1;
        if (it == NIT - 1) cp_wait<0>(); else cp_wait<1>();
        __syncthreads();

        const float* As = (const float*)(smem + buf * DN_STAGE);
        const float* Bs = As + 128 * A_PITCH_W;

#pragma unroll
        for (int s = 0; s < 4; s++) {
            const int k0 = 8 * s + c;
            uint32_t a[2][4];
#pragma unroll
            for (int mi = 0; mi < 2; mi++) {
                const float* ap = As + (wm * 32 + mi * 16 + g) * A_PITCH_W + k0;
                a[mi][0] = tf32r(ap[0]);
                a[mi][1] = tf32r(ap[8 * A_PITCH_W]);
                a[mi][2] = tf32r(ap[4]);
                a[mi][3] = tf32r(ap[8 * A_PITCH_W + 4]);
            }
#pragma unroll
            for (int ni = 0; ni < 8; ni++) {
                const float* bp = Bs + k0 * B128_PITCH_W + wn * 64 + ni * 8 + g;
                uint32_t b0 = tf32r(bp[0]), b1v = tf32r(bp[4 * B128_PITCH_W]);
                mma_tf32(acc[0][ni], a[0], b0, b1v);
                mma_tf32(acc[1][ni], a[1], b0, b1v);
            }
        }
        __syncthreads();
        if (it + 2 < NIT) load_stage(buf, (it + 2) * 32);
    }

    const int colbase = nt * 128 + wn * 64;
    const long long rowbase = (long long)e * TOK_PER_E + mt * 128 + wm * 32;
#pragma unroll
    for (int mi = 0; mi < 2; mi++) {
        const long long r0 = rowbase + mi * 16 + g;
#pragma unroll
        for (int ni = 0; ni < 8; ni++) {
            const int col = colbase + ni * 8 + 2 * c;
            float* p0 = out + r0 * DIM + col;
            float* p1 = p0 + 8 * DIM;
            *(float2*)p0 = make_float2(acc[mi][ni][0], acc[mi][ni][1]);
            *(float2*)p1 = make_float2(acc[mi][ni][2], acc[mi][ni][3]);
        }
    }
}

// ================= launch =================
extern "C" void kernel_launch(void* const* d_in, const int* in_sizes, int n_in,
                              void* d_out, int out_size)
{
    const float* x  = (const float*)d_in[0];
    const float* w1 = (const float*)d_in[1];
    const float* w2 = (const float*)d_in[2];
    const float* w3 = (const float*)d_in[3];
    float* out = (float*)d_out;

    float* h = nullptr;
    cudaGetSymbolAddress((void**)&h, g_h);

    static bool attr_done = false;
    if (!attr_done) {
        cudaFuncSetAttribute(moe_gateup, cudaFuncAttributeMaxDynamicSharedMemorySize, GU_SMEM);
        cudaFuncSetAttribute(moe_down, cudaFuncAttributeMaxDynamicSharedMemorySize, DN_SMEM);
        attr_done = true;
    }

    {
        dim3 grid(HIDDEN / 64, TOK_PER_E / 128, NUM_EXPERTS);  // (16, 2, 64)
        moe_gateup<<<grid, NTHREADS, GU_SMEM>>>(x, w1, w3, h);
    }
    {
        dim3 grid(DIM / 128, TOK_PER_E / 128, NUM_EXPERTS);    // (16, 2, 64)
        moe_down<<<grid, NTHREADS, DN_SMEM>>>(h, w2, out);
    }
}